// round 2
// baseline (speedup 1.0000x reference)
#include <cuda_runtime.h>
#include <math.h>

#define NHEAD 32
#define DDIM  128
#define KVLEN 32768
#define PAGE  16
#define NPAGE 2048
#define TOPK  256
#define HDIM  4096
#define SCALE 0.08838834764831845f   /* 1/sqrt(128) */

// ---------------- scratch (device globals; no allocations allowed) ----------
__device__ float g_qkv[3 * HDIM];        // q | k_new | v_new (q,k post-RoPE)
__device__ float g_sall[NHEAD * KVLEN];  // all scores, scaled (4 MB)
__device__ float g_est[NHEAD * NPAGE];   // page estimates
__device__ int   g_top[NHEAD * TOPK];    // selected page indices
__device__ float g_m[NHEAD];             // softmax max
__device__ float g_zinv[NHEAD];          // 1/Z
__device__ float g_o[NHEAD * DDIM];      // attention output

// ---------------- 0: zero atomic targets ------------------------------------
__global__ void k_init(float* __restrict__ out) {
    int t = blockIdx.x * blockDim.x + threadIdx.x;
    if (t < 3 * HDIM) g_qkv[t] = 0.f;
    if (t < HDIM)     out[t]   = 0.f;
}

// ---------------- 1: fused QKV GEMV (split-K, atomic accumulate) ------------
// grid = 3 mats * 32 colgroups * 8 rowgroups = 768 blocks, 128 threads
__global__ void k_qkv(const float* __restrict__ x,
                      const float* __restrict__ Wq,
                      const float* __restrict__ Wk,
                      const float* __restrict__ Wv) {
    int b  = blockIdx.x;
    int m  = b >> 8;           // matrix 0..2
    int r  = b & 255;
    int cg = r & 31;           // column group (128 cols)
    int rg = r >> 5;           // row group (512 rows)
    const float* W = (m == 0) ? Wq : (m == 1) ? Wk : Wv;

    int lane = threadIdx.x & 31;
    int wrp  = threadIdx.x >> 5;   // 4 warps, 128 rows each

    __shared__ float xs[512];
    for (int i = threadIdx.x; i < 512; i += 128) xs[i] = x[rg * 512 + i];
    __syncthreads();

    int col4 = cg * 32 + lane;               // float4 column index (0..1023)
    long i0  = (long)rg * 512 + wrp * 128;
    const float4* W4 = (const float4*)W;

    float4 acc = make_float4(0.f, 0.f, 0.f, 0.f);
#pragma unroll 8
    for (int i = 0; i < 128; i++) {
        float  xv = xs[wrp * 128 + i];
        float4 wv = __ldg(&W4[(i0 + i) * 1024 + col4]);
        acc.x += xv * wv.x; acc.y += xv * wv.y;
        acc.z += xv * wv.z; acc.w += xv * wv.w;
    }
    float* dst = &g_qkv[m * HDIM + col4 * 4];
    atomicAdd(dst + 0, acc.x); atomicAdd(dst + 1, acc.y);
    atomicAdd(dst + 2, acc.z); atomicAdd(dst + 3, acc.w);
}

// ---------------- 2: RoPE on q and k_new (pos = 32768) ----------------------
__global__ void k_rope() {
    int t = blockIdx.x * blockDim.x + threadIdx.x;   // 0..2047
    if (t >= NHEAD * 64) return;
    int h = t >> 6, i = t & 63;
    float inv = (float)pow(10000.0, -(double)i / 64.0);
    float ang = 32768.0f * inv;
    float s, c;
    sincosf(ang, &s, &c);
#pragma unroll
    for (int m = 0; m < 2; m++) {
        float* buf = &g_qkv[m * HDIM + h * DDIM];
        float a = buf[i], bb = buf[i + 64];
        buf[i]      = a * c - bb * s;
        buf[i + 64] = bb * c + a * s;
    }
}

// ---------------- 3: page min/max + est + ALL token scores (one pass) -------
// one warp per (page, head); grid 8192 x 256 threads
__global__ void k_scan(const float* __restrict__ kc) {
    int g    = blockIdx.x * 8 + (threadIdx.x >> 5);
    int lane = threadIdx.x & 31;
    int p = g >> 5, h = g & 31;

    const float4* k4 = (const float4*)kc;
    float4 q4 = ((const float4*)g_qkv)[h * 32 + lane];   // q[h, lane*4..+3]

    long base = ((long)p * 16 * 32 + h) * 32;            // float4 offset
    float4 mn = make_float4(0, 0, 0, 0), mx = mn;

#pragma unroll
    for (int t = 0; t < 16; t++) {
        float4 kv = __ldg(&k4[base + (long)t * 1024 + lane]);
        if (t == 0) { mn = kv; mx = kv; }
        else {
            mn.x = fminf(mn.x, kv.x); mn.y = fminf(mn.y, kv.y);
            mn.z = fminf(mn.z, kv.z); mn.w = fminf(mn.w, kv.w);
            mx.x = fmaxf(mx.x, kv.x); mx.y = fmaxf(mx.y, kv.y);
            mx.z = fmaxf(mx.z, kv.z); mx.w = fmaxf(mx.w, kv.w);
        }
        float d = q4.x * kv.x + q4.y * kv.y + q4.z * kv.z + q4.w * kv.w;
#pragma unroll
        for (int o = 16; o > 0; o >>= 1) d += __shfl_xor_sync(0xffffffffu, d, o);
        if (lane == 0) g_sall[h * KVLEN + p * 16 + t] = d * SCALE;
    }
    float e = fmaxf(q4.x * mn.x, q4.x * mx.x) + fmaxf(q4.y * mn.y, q4.y * mx.y)
            + fmaxf(q4.z * mn.z, q4.z * mx.z) + fmaxf(q4.w * mn.w, q4.w * mx.w);
#pragma unroll
    for (int o = 16; o > 0; o >>= 1) e += __shfl_xor_sync(0xffffffffu, e, o);
    if (lane == 0) g_est[h * NPAGE + p] = e;
}

// ---------------- 4: per-head top-256 of 2048 via bitonic sort ---------------
__global__ void k_topk() {
    __shared__ float sv[NPAGE];
    __shared__ int   si[NPAGE];
    int h = blockIdx.x, tid = threadIdx.x;   // 1024 threads
    for (int i = tid; i < NPAGE; i += 1024) {
        sv[i] = g_est[h * NPAGE + i];
        si[i] = i;
    }
    for (int k = 2; k <= NPAGE; k <<= 1) {
        for (int j = k >> 1; j > 0; j >>= 1) {
            __syncthreads();
            for (int i = tid; i < NPAGE; i += 1024) {
                int ixj = i ^ j;
                if (ixj > i) {
                    float va = sv[i], vb = sv[ixj];
                    int   ia = si[i], ib = si[ixj];
                    // "a ranks before b" in descending order (tie: lower idx)
                    bool aFirst = (va > vb) || (va == vb && ia < ib);
                    bool desc = ((i & k) == 0);
                    bool dosw = desc ? !aFirst : aFirst;
                    if (dosw) {
                        sv[i] = vb; sv[ixj] = va;
                        si[i] = ib; si[ixj] = ia;
                    }
                }
            }
        }
    }
    __syncthreads();
    if (tid < TOPK) g_top[h * TOPK + tid] = si[tid];
}

// ---------------- 5: softmax stats + init o with new-token term -------------
// 32 blocks (head) x 128 threads
__global__ void k_prep() {
    int h = blockIdx.x, tid = threadIdx.x;
    __shared__ float red[128];

    // s_new = (q . k_new) * scale
    float qd = g_qkv[h * DDIM + tid];
    float kd = g_qkv[HDIM + h * DDIM + tid];
    red[tid] = qd * kd;
    __syncthreads();
    for (int o = 64; o > 0; o >>= 1) {
        if (tid < o) red[tid] += red[tid + o];
        __syncthreads();
    }
    float s_new = red[0] * SCALE;
    __syncthreads();

    // max over selected scores (+ s_new)
    float mx = s_new;
    for (int k = tid; k < TOPK * PAGE; k += 128) {
        int page = g_top[h * TOPK + (k >> 4)];
        mx = fmaxf(mx, g_sall[h * KVLEN + page * 16 + (k & 15)]);
    }
    red[tid] = mx;
    __syncthreads();
    for (int o = 64; o > 0; o >>= 1) {
        if (tid < o) red[tid] = fmaxf(red[tid], red[tid + o]);
        __syncthreads();
    }
    float m = red[0];
    __syncthreads();

    // Z
    float z = (tid == 0) ? expf(s_new - m) : 0.f;
    for (int k = tid; k < TOPK * PAGE; k += 128) {
        int page = g_top[h * TOPK + (k >> 4)];
        z += expf(g_sall[h * KVLEN + page * 16 + (k & 15)] - m);
    }
    red[tid] = z;
    __syncthreads();
    for (int o = 64; o > 0; o >>= 1) {
        if (tid < o) red[tid] += red[tid + o];
        __syncthreads();
    }
    float Z = red[0];
    if (tid == 0) { g_m[h] = m; g_zinv[h] = 1.f / Z; }
    // init o with the new-token contribution
    g_o[h * DDIM + tid] = expf(s_new - m) / Z * g_qkv[2 * HDIM + h * DDIM + tid];
}

// ---------------- 6: weighted V gather-accumulate ----------------------------
// grid = 32 heads * 16 chunks (16 pages each); 128 threads (thread = dim)
__global__ void k_av(const float* __restrict__ vc) {
    int b = blockIdx.x;
    int h = b >> 4, ch = b & 15;
    int tid = threadIdx.x;
    __shared__ float ws[256];
    __shared__ int   ti[256];
    float m = g_m[h], zi = g_zinv[h];
    for (int k = tid; k < 256; k += 128) {
        int page = g_top[h * TOPK + ch * 16 + (k >> 4)];
        int tok  = page * 16 + (k & 15);
        ti[k] = tok;
        ws[k] = expf(g_sall[h * KVLEN + tok] - m) * zi;
    }
    __syncthreads();
    float acc = 0.f;
#pragma unroll 4
    for (int k = 0; k < 256; k++) {
        acc += ws[k] * __ldg(&vc[((long)ti[k] * 32 + h) * DDIM + tid]);
    }
    atomicAdd(&g_o[h * DDIM + tid], acc);
}

// ---------------- 7: output GEMV (split-K, atomic) ---------------------------
// grid = 32 colgroups * 16 rowgroups = 512 blocks, 128 threads
__global__ void k_out(const float* __restrict__ Wo, float* __restrict__ out) {
    int b  = blockIdx.x;
    int cg = b & 31;
    int rg = b >> 5;               // 16 rowgroups of 256 rows
    int lane = threadIdx.x & 31;
    int wrp  = threadIdx.x >> 5;   // 4 warps, 64 rows each

    __shared__ float os[256];
    for (int i = threadIdx.x; i < 256; i += 128) os[i] = g_o[rg * 256 + i];
    __syncthreads();

    long i0  = (long)rg * 256 + wrp * 64;
    int col4 = cg * 32 + lane;
    const float4* W4 = (const float4*)Wo;
    float4 acc = make_float4(0.f, 0.f, 0.f, 0.f);
#pragma unroll 8
    for (int i = 0; i < 64; i++) {
        float  xv = os[wrp * 64 + i];
        float4 wv = __ldg(&W4[(i0 + i) * 1024 + col4]);
        acc.x += xv * wv.x; acc.y += xv * wv.y;
        acc.z += xv * wv.z; acc.w += xv * wv.w;
    }
    float* dst = &out[col4 * 4];
    atomicAdd(dst + 0, acc.x); atomicAdd(dst + 1, acc.y);
    atomicAdd(dst + 2, acc.z); atomicAdd(dst + 3, acc.w);
}

// ---------------- launch ------------------------------------------------------
extern "C" void kernel_launch(void* const* d_in, const int* in_sizes, int n_in,
                              void* d_out, int out_size) {
    const float* x  = (const float*)d_in[0];
    const float* kc = (const float*)d_in[1];
    const float* vc = (const float*)d_in[2];
    const float* Wq = (const float*)d_in[3];
    const float* Wk = (const float*)d_in[4];
    const float* Wv = (const float*)d_in[5];
    const float* Wo = (const float*)d_in[6];
    float* out = (float*)d_out;

    k_init<<<48, 256>>>(out);
    k_qkv<<<768, 128>>>(x, Wq, Wk, Wv);
    k_rope<<<16, 128>>>();
    k_scan<<<8192, 256>>>(kc);
    k_topk<<<32, 1024>>>();
    k_prep<<<32, 128>>>();
    k_av<<<512, 128>>>(vc);
    k_out<<<512, 128>>>(Wo, out);
}